// round 16
// baseline (speedup 1.0000x reference)
#include <cuda_runtime.h>
#include <cuda_bf16.h>
#include <math.h>
#include <stdint.h>

#define M_ROWS 32768
#define KD     512
#define NC     2048
#define NSLOT  64
#define MARGIN 0.2f

// ---------------- device scratch (static; no allocation) -------------------
__device__ int8_t        g_z_q  [M_ROWS*KD];
__device__ float         g_s_z  [M_ROWS];
__device__ float         g_embn [NC*KD];
__device__ __nv_bfloat16 g_e_hi[NC*KD], g_e_mid[NC*KD], g_e_lo[NC*KD];
__device__ __nv_bfloat16 g_wt_hi[KD*KD], g_wt_mid[KD*KD], g_wt_lo[KD*KD];
__device__ __nv_bfloat16 g_wout_hi[KD*KD], g_wout_lo[KD*KD];
__device__ float         g_G   [NC*KD];
__device__ int8_t        g_G_q [NC*KD];
__device__ float         g_s_g [NC];
__device__ float         g_c   [NC];
__device__ float         g_table[NC*KD];
__device__ unsigned      g_rowmax[M_ROWS];
__device__ int           g_ccnt[M_ROWS];
__device__ int           g_cand[M_ROWS*NSLOT];

// ---------------- PTX helpers ----------------------------------------------
__device__ __forceinline__ uint32_t smem_u32(const void* p) {
    uint32_t a;
    asm("{ .reg .u64 t; cvta.to.shared.u64 t, %1; cvt.u32.u64 %0, t; }" : "=r"(a) : "l"(p));
    return a;
}
#define CP_ASYNC16(dst, src) \
    asm volatile("cp.async.cg.shared.global [%0], [%1], 16;" :: "r"(dst), "l"(src) : "memory")
#define CP_COMMIT()  asm volatile("cp.async.commit_group;" ::: "memory")
#define CP_WAIT(n)   asm volatile("cp.async.wait_group %0;" :: "n"(n) : "memory")

__device__ __forceinline__ void ldmx4(uint32_t* r, uint32_t addr) {
    asm volatile("ldmatrix.sync.aligned.m8n8.x4.shared.b16 {%0,%1,%2,%3}, [%4];"
                 : "=r"(r[0]), "=r"(r[1]), "=r"(r[2]), "=r"(r[3]) : "r"(addr));
}
__device__ __forceinline__ void mma_bf16(float* c, const uint32_t* a, const uint32_t* b) {
    asm volatile("mma.sync.aligned.m16n8k16.row.col.f32.bf16.bf16.f32 "
                 "{%0,%1,%2,%3}, {%4,%5,%6,%7}, {%8,%9}, {%0,%1,%2,%3};"
                 : "+f"(c[0]), "+f"(c[1]), "+f"(c[2]), "+f"(c[3])
                 : "r"(a[0]), "r"(a[1]), "r"(a[2]), "r"(a[3]), "r"(b[0]), "r"(b[1]));
}
__device__ __forceinline__ void mma_s8(int* c, const uint32_t* a, const uint32_t* b) {
    asm volatile("mma.sync.aligned.m16n8k32.row.col.s32.s8.s8.s32 "
                 "{%0,%1,%2,%3}, {%4,%5,%6,%7}, {%8,%9}, {%0,%1,%2,%3};"
                 : "+r"(c[0]), "+r"(c[1]), "+r"(c[2]), "+r"(c[3])
                 : "r"(a[0]), "r"(a[1]), "r"(a[2]), "r"(a[3]), "r"(b[0]), "r"(b[1]));
}

__device__ __forceinline__ unsigned fenc(float x) {
    unsigned u = __float_as_uint(x);
    return (u & 0x80000000u) ? ~u : (u | 0x80000000u);
}
__device__ __forceinline__ float fdec(unsigned u) {
    u = (u & 0x80000000u) ? (u & 0x7fffffffu) : ~u;
    return __uint_as_float(u);
}

// ---------------- prep kernels ----------------------------------------------
// per-row int8 quantization: warp per row (cols = 512)
__global__ void quant_rows_kernel(const float* __restrict__ src,
                                  int8_t* __restrict__ dst,
                                  float* __restrict__ scale) {
    int warp = threadIdx.x >> 5, lane = threadIdx.x & 31;
    int row = blockIdx.x * 8 + warp;
    const float4* sr = (const float4*)(src + (size_t)row * KD);
    float4 v[4];
    float amax = 0.f;
    #pragma unroll
    for (int j = 0; j < 4; j++) {
        v[j] = sr[lane + 32 * j];
        amax = fmaxf(amax, fmaxf(fmaxf(fabsf(v[j].x), fabsf(v[j].y)),
                                 fmaxf(fabsf(v[j].z), fabsf(v[j].w))));
    }
    #pragma unroll
    for (int o = 16; o > 0; o >>= 1) amax = fmaxf(amax, __shfl_xor_sync(0xffffffffu, amax, o));
    amax = fmaxf(amax, 1e-8f);
    float inv = 127.0f / amax;
    if (lane == 0) scale[row] = amax / 127.0f;
    uint32_t* dr = (uint32_t*)(dst + (size_t)row * KD);
    #pragma unroll
    for (int j = 0; j < 4; j++) {
        int q0 = __float2int_rn(v[j].x * inv);
        int q1 = __float2int_rn(v[j].y * inv);
        int q2 = __float2int_rn(v[j].z * inv);
        int q3 = __float2int_rn(v[j].w * inv);
        uint32_t p = (uint32_t)(q0 & 0xff) | ((uint32_t)(q1 & 0xff) << 8)
                   | ((uint32_t)(q2 & 0xff) << 16) | ((uint32_t)(q3 & 0xff) << 24);
        dr[lane + 32 * j] = p;
    }
}

__global__ void split2_kernel(const float* __restrict__ src,
                              __nv_bfloat16* __restrict__ hi,
                              __nv_bfloat16* __restrict__ lo, int n4) {
    for (int i = blockIdx.x * 256 + threadIdx.x; i < n4; i += gridDim.x * 256) {
        float4 v = ((const float4*)src)[i];
        __nv_bfloat16 h[4], l[4];
        float a[4] = {v.x, v.y, v.z, v.w};
        #pragma unroll
        for (int k = 0; k < 4; k++) {
            h[k] = __float2bfloat16_rn(a[k]);
            l[k] = __float2bfloat16_rn(a[k] - __bfloat162float(h[k]));
        }
        ((uint2*)hi)[i] = *(uint2*)h;
        ((uint2*)lo)[i] = *(uint2*)l;
    }
}

__global__ void zero_state_kernel(unsigned* __restrict__ r, int* __restrict__ cnt) {
    int i = blockIdx.x * 256 + threadIdx.x;
    if (i < M_ROWS) { r[i] = 0u; cnt[i] = 0; }
}

__global__ void rownorm_split3_kernel(const float* __restrict__ in,
                                      float* __restrict__ outF,
                                      __nv_bfloat16* __restrict__ hi,
                                      __nv_bfloat16* __restrict__ mid,
                                      __nv_bfloat16* __restrict__ lo) {
    int row = blockIdx.x;
    float4 v = ((const float4*)(in + (size_t)row * KD))[threadIdx.x];
    float ss = v.x*v.x + v.y*v.y + v.z*v.z + v.w*v.w;
    #pragma unroll
    for (int o = 16; o > 0; o >>= 1) ss += __shfl_down_sync(0xffffffffu, ss, o);
    __shared__ float red[4];
    if ((threadIdx.x & 31) == 0) red[threadIdx.x >> 5] = ss;
    __syncthreads();
    float n = fmaxf(sqrtf(red[0] + red[1] + red[2] + red[3]), 1e-12f);
    v.x /= n; v.y /= n; v.z /= n; v.w /= n;
    ((float4*)(outF + (size_t)row * KD))[threadIdx.x] = v;
    float a[4] = {v.x, v.y, v.z, v.w};
    __nv_bfloat16 h[4], m[4], l[4];
    #pragma unroll
    for (int k = 0; k < 4; k++) {
        h[k] = __float2bfloat16_rn(a[k]);
        float r1 = a[k] - __bfloat162float(h[k]);
        m[k] = __float2bfloat16_rn(r1);
        l[k] = __float2bfloat16_rn(r1 - __bfloat162float(m[k]));
    }
    size_t off = (size_t)row * KD + threadIdx.x * 4;
    *(uint2*)(hi + off)  = *(uint2*)h;
    *(uint2*)(mid + off) = *(uint2*)m;
    *(uint2*)(lo + off)  = *(uint2*)l;
}

__global__ void transpose_split3_kernel(const float* __restrict__ W,
                                        __nv_bfloat16* __restrict__ hi,
                                        __nv_bfloat16* __restrict__ mid,
                                        __nv_bfloat16* __restrict__ lo) {
    __shared__ float t[32][33];
    int bl = blockIdx.x * 32, be = blockIdx.y * 32;
    int tx = threadIdx.x, ty = threadIdx.y;
    #pragma unroll
    for (int i = 0; i < 32; i += 8)
        t[ty + i][tx] = W[(size_t)(be + ty + i) * KD + bl + tx];
    __syncthreads();
    #pragma unroll
    for (int i = 0; i < 32; i += 8) {
        float a = t[tx][ty + i];
        size_t o = (size_t)(bl + ty + i) * KD + be + tx;
        __nv_bfloat16 h = __float2bfloat16_rn(a);
        float r1 = a - __bfloat162float(h);
        __nv_bfloat16 m = __float2bfloat16_rn(r1);
        __nv_bfloat16 l = __float2bfloat16_rn(r1 - __bfloat162float(m));
        hi[o] = h; mid[o] = m; lo[o] = l;
    }
}

__global__ void cvec_kernel(const float* __restrict__ embn,
                            const float* __restrict__ b_in, float* __restrict__ c) {
    int n = blockIdx.x, lane = threadIdx.x;
    float s = 0.f;
    for (int i = lane; i < KD; i += 32) s += embn[(size_t)n * KD + i] * b_in[i];
    #pragma unroll
    for (int o = 16; o > 0; o >>= 1) s += __shfl_down_sync(0xffffffffu, s, o);
    if (lane == 0) c[n] = s;
}

// ---------------- bf16 smem tile + mma (for small fp32 GEMMs) --------------
__device__ __forceinline__ void load_tile_ca(const __nv_bfloat16* __restrict__ src,
                                             int rowBase, int kc, uint32_t dstBase, int tid) {
    #pragma unroll
    for (int u = 0; u < 2; u++) {
        int e = tid + u * 256;
        int r = e >> 2, c = e & 3;
        const __nv_bfloat16* g = src + (size_t)(rowBase + r) * KD + kc + c * 8;
        CP_ASYNC16(dstBase + r * 64 + ((c ^ ((r >> 1) & 3)) * 16), g);
    }
}

__device__ __forceinline__ void mma_pair(uint32_t stA, uint32_t stB,
                                         int lane, int warp_m, int warp_n, int ks,
                                         float acc[4][4][4]) {
    uint32_t a[4][4], b[4][2];
    #pragma unroll
    for (int mi = 0; mi < 4; mi++) {
        int row = warp_m * 64 + mi * 16 + (lane & 15);
        int ch  = ks * 2 + (lane >> 4);
        ldmx4(a[mi], stA + row * 64 + ((ch ^ ((row >> 1) & 3)) * 16));
    }
    #pragma unroll
    for (int p = 0; p < 2; p++) {
        int g = lane >> 3;
        int row = warp_n * 32 + p * 16 + ((g & 2) << 2) + (lane & 7);
        int ch  = ks * 2 + (g & 1);
        uint32_t r[4];
        ldmx4(r, stB + row * 64 + ((ch ^ ((row >> 1) & 3)) * 16));
        b[2*p][0] = r[0]; b[2*p][1] = r[1];
        b[2*p+1][0] = r[2]; b[2*p+1][1] = r[3];
    }
    #pragma unroll
    for (int mi = 0; mi < 4; mi++)
        #pragma unroll
        for (int ni = 0; ni < 4; ni++)
            mma_bf16(acc[mi][ni], a[mi], b[ni]);
}

// ---------------- general GEMM (128x128 tile, 2-stage, bf16) ---------------
template<int TERMS, bool BIAS>
__global__ void __launch_bounds__(256) vq_gemm_kernel(
        const __nv_bfloat16* __restrict__ A0, const __nv_bfloat16* __restrict__ A1,
        const __nv_bfloat16* __restrict__ A2,
        const __nv_bfloat16* __restrict__ B0, const __nv_bfloat16* __restrict__ B1,
        const __nv_bfloat16* __restrict__ B2,
        const float* __restrict__ bias, float* __restrict__ C, int Ncols) {
    extern __shared__ char smem[];
    const int NL    = (TERMS == 6) ? 3 : (TERMS == 3) ? 2 : 1;
    const int STAGE = NL * 2 * 8192;
    uint32_t sb = smem_u32(smem);
    int tid = threadIdx.x, lane = tid & 31, wid = tid >> 5;
    int warp_m = wid & 1, warp_n = wid >> 1;
    int rowBase = blockIdx.y * 128;
    int colBase = blockIdx.x * 128;

    const __nv_bfloat16* As[3] = {A0, A1, A2};
    const __nv_bfloat16* Bs[3] = {B0, B1, B2};

    float acc[4][4][4];
    #pragma unroll
    for (int mi = 0; mi < 4; mi++)
        #pragma unroll
        for (int ni = 0; ni < 4; ni++)
            #pragma unroll
            for (int q = 0; q < 4; q++) acc[mi][ni][q] = 0.0f;

    #pragma unroll
    for (int l = 0; l < NL; l++) {
        load_tile_ca(As[l], rowBase, 0, sb + (2*l)   * 8192, tid);
        load_tile_ca(Bs[l], colBase, 0, sb + (2*l+1) * 8192, tid);
    }
    CP_COMMIT();

    const int KT = KD / 32;
    for (int kt = 0; kt < KT; kt++) {
        int s = kt & 1;
        if (kt + 1 < KT) {
            uint32_t st = sb + (s ^ 1) * STAGE;
            int kc = (kt + 1) * 32;
            #pragma unroll
            for (int l = 0; l < NL; l++) {
                load_tile_ca(As[l], rowBase, kc, st + (2*l)   * 8192, tid);
                load_tile_ca(Bs[l], colBase, kc, st + (2*l+1) * 8192, tid);
            }
            CP_COMMIT();
            CP_WAIT(1);
        } else {
            CP_WAIT(0);
        }
        __syncthreads();

        uint32_t st = sb + s * STAGE;
        uint32_t tA[3], tB[3];
        #pragma unroll
        for (int l = 0; l < NL; l++) { tA[l] = st + (2*l)*8192; tB[l] = st + (2*l+1)*8192; }

        #pragma unroll
        for (int ks = 0; ks < 2; ks++) {
            mma_pair(tA[0], tB[0], lane, warp_m, warp_n, ks, acc);
            if (TERMS >= 3) {
                mma_pair(tA[0], tB[NL-1], lane, warp_m, warp_n, ks, acc);
                mma_pair(tA[NL-1], tB[0], lane, warp_m, warp_n, ks, acc);
            }
            if (TERMS == 6) {
                mma_pair(tA[0], tB[1], lane, warp_m, warp_n, ks, acc);
                mma_pair(tA[1], tB[0], lane, warp_m, warp_n, ks, acc);
                mma_pair(tA[1], tB[1], lane, warp_m, warp_n, ks, acc);
            }
        }
        __syncthreads();
    }

    #pragma unroll
    for (int mi = 0; mi < 4; mi++) {
        int r0 = rowBase + warp_m * 64 + mi * 16 + (lane >> 2);
        #pragma unroll
        for (int ni = 0; ni < 4; ni++) {
            int col = colBase + warp_n * 32 + ni * 8 + (lane & 3) * 2;
            float b0 = BIAS ? bias[col]     : 0.0f;
            float b1 = BIAS ? bias[col + 1] : 0.0f;
            float2 v0 = {acc[mi][ni][0] + b0, acc[mi][ni][1] + b1};
            float2 v1 = {acc[mi][ni][2] + b0, acc[mi][ni][3] + b1};
            *(float2*)(C + (size_t)r0 * Ncols + col)       = v0;
            *(float2*)(C + (size_t)(r0 + 8) * Ncols + col) = v1;
        }
    }
}

// ---------------- int8 scores GEMM: 128x128 tile, 2-stage ------------------
// Tile = 128 rows x 64 int8 (64B/row, same swizzle & addressing as bf16).
// mma.m16n8k32.s8 at 2x bf16 rate; KT = 8. Epilogue converts acc to fp32 with
// per-row scales, then fused rowmax + candidate push (MARGIN 0.2 ~= 13 sigma
// of int8 screening error; exact fp32 rerank makes the final decision).
__device__ __forceinline__ void load_tile_s8(const int8_t* __restrict__ src,
                                             int rowBase, int kc, uint32_t dstBase, int tid) {
    #pragma unroll
    for (int u = 0; u < 2; u++) {
        int e = tid + u * 256;
        int r = e >> 2, c = e & 3;
        const int8_t* g = src + (size_t)(rowBase + r) * KD + kc + c * 16;
        CP_ASYNC16(dstBase + r * 64 + ((c ^ ((r >> 1) & 3)) * 16), g);
    }
}

__global__ void __launch_bounds__(256) vq_score_kernel(
        const int8_t* __restrict__ A, const int8_t* __restrict__ B,
        const float* __restrict__ sZ, const float* __restrict__ sG,
        const float* __restrict__ cvec, unsigned* __restrict__ rowMax,
        int* __restrict__ ccnt, int* __restrict__ cand) {
    extern __shared__ char smem[];
    const int STAGE = 16384;
    uint32_t sb = smem_u32(smem);
    int tid = threadIdx.x, lane = tid & 31, wid = tid >> 5;
    int warp_m = wid & 1, warp_n = wid >> 1;
    int rowBase = blockIdx.x * 128;
    int colBase = blockIdx.y * 128;

    int acc[4][4][4];
    #pragma unroll
    for (int mi = 0; mi < 4; mi++)
        #pragma unroll
        for (int ni = 0; ni < 4; ni++)
            #pragma unroll
            for (int q = 0; q < 4; q++) acc[mi][ni][q] = 0;

    load_tile_s8(A, rowBase, 0, sb, tid);
    load_tile_s8(B, colBase, 0, sb + 8192, tid);
    CP_COMMIT();

    const int KT = KD / 64;   // 8
    for (int kt = 0; kt < KT; kt++) {
        int s = kt & 1;
        if (kt + 1 < KT) {
            uint32_t st = sb + (s ^ 1) * STAGE;
            load_tile_s8(A, rowBase, (kt + 1) * 64, st, tid);
            load_tile_s8(B, colBase, (kt + 1) * 64, st + 8192, tid);
            CP_COMMIT();
            CP_WAIT(1);
        } else {
            CP_WAIT(0);
        }
        __syncthreads();

        uint32_t stA = sb + s * STAGE;
        uint32_t stB = stA + 8192;
        #pragma unroll
        for (int ks = 0; ks < 2; ks++) {    // two k32 slices per 64-int8 tile
            uint32_t a[4][4], b[4][2];
            #pragma unroll
            for (int mi = 0; mi < 4; mi++) {
                int row = warp_m * 64 + mi * 16 + (lane & 15);
                int ch  = ks * 2 + (lane >> 4);
                ldmx4(a[mi], stA + row * 64 + ((ch ^ ((row >> 1) & 3)) * 16));
            }
            #pragma unroll
            for (int p = 0; p < 2; p++) {
                int g = lane >> 3;
                int row = warp_n * 32 + p * 16 + ((g & 2) << 2) + (lane & 7);
                int ch  = ks * 2 + (g & 1);
                uint32_t r[4];
                ldmx4(r, stB + row * 64 + ((ch ^ ((row >> 1) & 3)) * 16));
                b[2*p][0] = r[0]; b[2*p][1] = r[1];
                b[2*p+1][0] = r[2]; b[2*p+1][1] = r[3];
            }
            #pragma unroll
            for (int mi = 0; mi < 4; mi++)
                #pragma unroll
                for (int ni = 0; ni < 4; ni++)
                    mma_s8(acc[mi][ni], a[mi], b[ni]);
        }
        __syncthreads();
    }

    // convert to fp32 scores: s = acc * sZ[row]*sG[col] + cvec[col]
    float fac[4][4][4];
    float szr[4][2];
    #pragma unroll
    for (int mi = 0; mi < 4; mi++) {
        int rl = warp_m * 64 + mi * 16 + (lane >> 2);
        szr[mi][0] = sZ[rowBase + rl];
        szr[mi][1] = sZ[rowBase + rl + 8];
    }
    #pragma unroll
    for (int ni = 0; ni < 4; ni++) {
        int col = colBase + warp_n * 32 + ni * 8 + (lane & 3) * 2;
        float g0 = sG[col], g1 = sG[col + 1];
        float c0 = cvec[col], c1 = cvec[col + 1];
        #pragma unroll
        for (int mi = 0; mi < 4; mi++) {
            fac[mi][ni][0] = (float)acc[mi][ni][0] * (szr[mi][0] * g0) + c0;
            fac[mi][ni][1] = (float)acc[mi][ni][1] * (szr[mi][0] * g1) + c1;
            fac[mi][ni][2] = (float)acc[mi][ni][2] * (szr[mi][1] * g0) + c0;
            fac[mi][ni][3] = (float)acc[mi][ni][3] * (szr[mi][1] * g1) + c1;
        }
    }

    unsigned* rmax = (unsigned*)smem;
    if (tid < 128) rmax[tid] = 0u;
    __syncthreads();
    #pragma unroll
    for (int mi = 0; mi < 4; mi++) {
        int rl = warp_m * 64 + mi * 16 + (lane >> 2);
        float m0 = -1e30f, m1 = -1e30f;
        #pragma unroll
        for (int ni = 0; ni < 4; ni++) {
            m0 = fmaxf(m0, fmaxf(fac[mi][ni][0], fac[mi][ni][1]));
            m1 = fmaxf(m1, fmaxf(fac[mi][ni][2], fac[mi][ni][3]));
        }
        atomicMax(&rmax[rl],     fenc(m0));
        atomicMax(&rmax[rl + 8], fenc(m1));
    }
    __syncthreads();
    if (tid < 128) {
        unsigned mine = rmax[tid];
        unsigned old = atomicMax(&rowMax[rowBase + tid], mine);
        rmax[tid] = (old > mine) ? old : mine;
    }
    __syncthreads();
    #pragma unroll
    for (int mi = 0; mi < 4; mi++) {
        int rl = warp_m * 64 + mi * 16 + (lane >> 2);
        int r0 = rowBase + rl, r1 = r0 + 8;
        float t0 = fdec(rmax[rl]) - MARGIN;
        float t1 = fdec(rmax[rl + 8]) - MARGIN;
        #pragma unroll
        for (int ni = 0; ni < 4; ni++) {
            int col = colBase + warp_n * 32 + ni * 8 + (lane & 3) * 2;
            if (fac[mi][ni][0] >= t0) { int q = atomicAdd(&ccnt[r0], 1); if (q < NSLOT) cand[r0*NSLOT+q] = col; }
            if (fac[mi][ni][1] >= t0) { int q = atomicAdd(&ccnt[r0], 1); if (q < NSLOT) cand[r0*NSLOT+q] = col+1; }
            if (fac[mi][ni][2] >= t1) { int q = atomicAdd(&ccnt[r1], 1); if (q < NSLOT) cand[r1*NSLOT+q] = col; }
            if (fac[mi][ni][3] >= t1) { int q = atomicAdd(&ccnt[r1], 1); if (q < NSLOT) cand[r1*NSLOT+q] = col+1; }
        }
    }
}

// ---------------- rerank + fused output gather ------------------------------
__global__ void __launch_bounds__(256) rerank_gather_kernel(
        const int* __restrict__ ccnt, const int* __restrict__ cand,
        const float* __restrict__ z, const float* __restrict__ G,
        const float* __restrict__ cvec, const float* __restrict__ table,
        float* __restrict__ out, float* __restrict__ outTail) {
    int warp = threadIdx.x >> 5, lane = threadIdx.x & 31;
    int row = blockIdx.x * 8 + warp;

    int nc = ccnt[row];
    int bi;
    if (nc == 1) {
        bi = cand[row * NSLOT];
    } else {
        float zreg[16];
        const float* zr = z + (size_t)row * KD;
        #pragma unroll
        for (int k = 0; k < 16; k++) zreg[k] = zr[lane + 32 * k];
        float best = -1e30f; bi = 0x7fffffff;
        if (nc <= NSLOT) {
            for (int c = 0; c < nc; c++) {
                int ci = cand[row * NSLOT + c];
                const float* g = G + (size_t)ci * KD;
                float d = 0.f;
                #pragma unroll
                for (int k = 0; k < 16; k++) d = fmaf(zreg[k], g[lane + 32 * k], d);
                #pragma unroll
                for (int o = 16; o > 0; o >>= 1) d += __shfl_xor_sync(0xffffffffu, d, o);
                d += cvec[ci];
                if (d > best || (d == best && ci < bi)) { best = d; bi = ci; }
            }
        } else {
            for (int ci = 0; ci < NC; ci++) {
                const float* g = G + (size_t)ci * KD;
                float d = 0.f;
                #pragma unroll
                for (int k = 0; k < 16; k++) d = fmaf(zreg[k], g[lane + 32 * k], d);
                #pragma unroll
                for (int o = 16; o > 0; o >>= 1) d += __shfl_xor_sync(0xffffffffu, d, o);
                d += cvec[ci];
                if (d > best) { best = d; bi = ci; }
            }
        }
    }

    const float4* src = (const float4*)(table + (size_t)bi * KD);
    float4* dst = (float4*)(out + (size_t)row * KD);
    #pragma unroll
    for (int j = 0; j < 4; j++) dst[lane + 32 * j] = src[lane + 32 * j];
    if (outTail && lane == 0) outTail[row] = (float)bi;
}

// ---------------------------------------------------------------------------
extern "C" void kernel_launch(void* const* d_in, const int* in_sizes, int n_in,
                              void* d_out, int out_size) {
    const float* z     = (const float*)d_in[0];
    const float* W_in  = (const float*)d_in[2];
    const float* b_in  = (const float*)d_in[3];
    const float* W_out = (const float*)d_in[4];
    const float* b_out = (const float*)d_in[5];
    const float* emb   = (const float*)d_in[6];
    float* out = (float*)d_out;

    __nv_bfloat16 *e_hi, *e_mid, *e_lo, *wt_hi, *wt_mid, *wt_lo;
    __nv_bfloat16 *wout_hi, *wout_lo;
    int8_t *z_q, *G_q;
    float *embn, *G, *cvec, *table, *s_z, *s_g;
    unsigned* rowmax;
    int *ccnt, *cand;
    cudaGetSymbolAddress((void**)&z_q,    g_z_q);
    cudaGetSymbolAddress((void**)&s_z,    g_s_z);
    cudaGetSymbolAddress((void**)&embn,   g_embn);
    cudaGetSymbolAddress((void**)&e_hi,   g_e_hi);
    cudaGetSymbolAddress((void**)&e_mid,  g_e_mid);
    cudaGetSymbolAddress((void**)&e_lo,   g_e_lo);
    cudaGetSymbolAddress((void**)&wt_hi,  g_wt_hi);
    cudaGetSymbolAddress((void**)&wt_mid, g_wt_mid);
    cudaGetSymbolAddress((void**)&wt_lo,  g_wt_lo);
    cudaGetSymbolAddress((void**)&wout_hi,g_wout_hi);
    cudaGetSymbolAddress((void**)&wout_lo,g_wout_lo);
    cudaGetSymbolAddress((void**)&G,      g_G);
    cudaGetSymbolAddress((void**)&G_q,    g_G_q);
    cudaGetSymbolAddress((void**)&s_g,    g_s_g);
    cudaGetSymbolAddress((void**)&cvec,   g_c);
    cudaGetSymbolAddress((void**)&table,  g_table);
    cudaGetSymbolAddress((void**)&rowmax, g_rowmax);
    cudaGetSymbolAddress((void**)&ccnt,   g_ccnt);
    cudaGetSymbolAddress((void**)&cand,   g_cand);

    const int SM_T6 = 2 * 6 * 8192;
    const int SM_T3 = 2 * 4 * 8192;
    const int SM_SC = 2 * 16384;
    cudaFuncSetAttribute(vq_gemm_kernel<6, false>, cudaFuncAttributeMaxDynamicSharedMemorySize, SM_T6);
    cudaFuncSetAttribute(vq_gemm_kernel<3, true >, cudaFuncAttributeMaxDynamicSharedMemorySize, SM_T3);
    cudaFuncSetAttribute(vq_score_kernel, cudaFuncAttributeMaxDynamicSharedMemorySize, SM_SC);

    // prep
    rownorm_split3_kernel<<<NC, 128>>>(emb, embn, e_hi, e_mid, e_lo);
    transpose_split3_kernel<<<dim3(16, 16), dim3(32, 8)>>>(W_in, wt_hi, wt_mid, wt_lo);
    cvec_kernel<<<NC, 32>>>(embn, b_in, cvec);
    quant_rows_kernel<<<M_ROWS / 8, 256>>>(z, z_q, s_z);
    split2_kernel<<<256, 256>>>(W_out, wout_hi, wout_lo, KD * KD / 4);
    zero_state_kernel<<<M_ROWS / 256, 256>>>(rowmax, ccnt);

    // G = embn @ W_in  (fp32-grade via 6-term), then int8 quantize
    vq_gemm_kernel<6, false><<<dim3(4, 16), 256, SM_T6>>>(
        e_hi, e_mid, e_lo, wt_hi, wt_mid, wt_lo, nullptr, G, KD);
    quant_rows_kernel<<<NC / 8, 256>>>(G, G_q, s_g);

    // code table T = embn @ W_out^T + b_out  (A split = (hi, mid))
    vq_gemm_kernel<3, true><<<dim3(4, 16), 256, SM_T3>>>(
        e_hi, e_mid, nullptr, wout_hi, wout_lo, nullptr, b_out, table, KD);

    // int8 scores GEMM with fused rowmax + candidate push
    vq_score_kernel<<<dim3(256, 16), 256, SM_SC>>>(
        z_q, G_q, s_z, s_g, cvec, rowmax, ccnt, cand);

    // rerank (nc==1 fast path) + fused output gather + index tail
    float* outTail = (out_size >= M_ROWS * KD + M_ROWS) ? (out + (size_t)M_ROWS * KD) : nullptr;
    rerank_gather_kernel<<<M_ROWS / 8, 256>>>(
        ccnt, cand, z, G, cvec, table, out, outTail);
}

// round 17
// speedup vs baseline: 1.8248x; 1.8248x over previous
#include <cuda_runtime.h>
#include <cuda_bf16.h>
#include <math.h>
#include <stdint.h>

#define M_ROWS 32768
#define KD     512
#define NC     2048
#define NSLOT  64
#define MARGIN 0.04f

// ---------------- device scratch (static; no allocation) -------------------
__device__ __nv_bfloat16 g_z_bf  [M_ROWS*KD];
__device__ float         g_embn  [NC*KD];
__device__ __nv_bfloat16 g_e_hi[NC*KD], g_e_mid[NC*KD], g_e_lo[NC*KD];
__device__ __nv_bfloat16 g_wt_hi[KD*KD], g_wt_mid[KD*KD], g_wt_lo[KD*KD];
__device__ __nv_bfloat16 g_wout_hi[KD*KD], g_wout_lo[KD*KD];
__device__ float         g_G   [NC*KD];
__device__ __nv_bfloat16 g_G_bf[NC*KD];
__device__ float         g_c   [NC];
__device__ float         g_table[NC*KD];
__device__ unsigned      g_rowmax[M_ROWS];
__device__ int           g_ccnt[M_ROWS];
__device__ int           g_cand[M_ROWS*NSLOT];

// ---------------- PTX helpers ----------------------------------------------
__device__ __forceinline__ uint32_t smem_u32(const void* p) {
    uint32_t a;
    asm("{ .reg .u64 t; cvta.to.shared.u64 t, %1; cvt.u32.u64 %0, t; }" : "=r"(a) : "l"(p));
    return a;
}
#define CP_ASYNC16(dst, src) \
    asm volatile("cp.async.cg.shared.global [%0], [%1], 16;" :: "r"(dst), "l"(src) : "memory")
#define CP_COMMIT()  asm volatile("cp.async.commit_group;" ::: "memory")
#define CP_WAIT(n)   asm volatile("cp.async.wait_group %0;" :: "n"(n) : "memory")

__device__ __forceinline__ void ldmx4(uint32_t* r, uint32_t addr) {
    asm volatile("ldmatrix.sync.aligned.m8n8.x4.shared.b16 {%0,%1,%2,%3}, [%4];"
                 : "=r"(r[0]), "=r"(r[1]), "=r"(r[2]), "=r"(r[3]) : "r"(addr));
}
__device__ __forceinline__ void mma_bf16(float* c, const uint32_t* a, const uint32_t* b) {
    asm volatile("mma.sync.aligned.m16n8k16.row.col.f32.bf16.bf16.f32 "
                 "{%0,%1,%2,%3}, {%4,%5,%6,%7}, {%8,%9}, {%0,%1,%2,%3};"
                 : "+f"(c[0]), "+f"(c[1]), "+f"(c[2]), "+f"(c[3])
                 : "r"(a[0]), "r"(a[1]), "r"(a[2]), "r"(a[3]), "r"(b[0]), "r"(b[1]));
}

__device__ __forceinline__ unsigned fenc(float x) {
    unsigned u = __float_as_uint(x);
    return (u & 0x80000000u) ? ~u : (u | 0x80000000u);
}
__device__ __forceinline__ float fdec(unsigned u) {
    u = (u & 0x80000000u) ? (u & 0x7fffffffu) : ~u;
    return __uint_as_float(u);
}

// ---------------- fused prep kernel -----------------------------------------
// Block-range dispatch (all sections independent):
//   [0, 1024)        rownorm + 3-way split of emb (2 rows per block)
//   [1024, 1280)     W_in transpose + 3-way split (32x32 tiles)
//   [1280, 1536)     cvec: c[n] = embn_n . b_in (8 warps = 8 rows per block)
//                    NOTE reads g_embn written by section A of OTHER blocks?
//                    -> NO: cvec recomputes the normalization locally from emb.
//   [1536, 1792)     W_out 2-way split
//   [1792, 1920)     zero rowmax / ccnt
//   [1920, 3200)     z -> bf16 (grid-stride over 4M float4)
__global__ void __launch_bounds__(256) prep_kernel(
        const float* __restrict__ z, const float* __restrict__ emb,
        const float* __restrict__ W_in, const float* __restrict__ b_in,
        const float* __restrict__ W_out,
        float* __restrict__ embn,
        __nv_bfloat16* __restrict__ e_hi, __nv_bfloat16* __restrict__ e_mid,
        __nv_bfloat16* __restrict__ e_lo,
        __nv_bfloat16* __restrict__ wt_hi, __nv_bfloat16* __restrict__ wt_mid,
        __nv_bfloat16* __restrict__ wt_lo,
        __nv_bfloat16* __restrict__ wout_hi, __nv_bfloat16* __restrict__ wout_lo,
        float* __restrict__ cvec,
        unsigned* __restrict__ rowmax, int* __restrict__ ccnt,
        __nv_bfloat16* __restrict__ z_bf) {
    int blk = blockIdx.x;
    int tid = threadIdx.x;

    if (blk < 1024) {
        // --- rownorm + split3 of emb: 2 rows per block (128 threads each) ---
        __shared__ float red[2][4];
        int half = tid >> 7;          // 0 or 1
        int t    = tid & 127;
        int row  = blk * 2 + half;
        float4 v = ((const float4*)(emb + (size_t)row * KD))[t];
        float ss = v.x*v.x + v.y*v.y + v.z*v.z + v.w*v.w;
        #pragma unroll
        for (int o = 16; o > 0; o >>= 1) ss += __shfl_down_sync(0xffffffffu, ss, o);
        if ((t & 31) == 0) red[half][t >> 5] = ss;
        __syncthreads();
        float n = fmaxf(sqrtf(red[half][0] + red[half][1] + red[half][2] + red[half][3]), 1e-12f);
        v.x /= n; v.y /= n; v.z /= n; v.w /= n;
        ((float4*)(embn + (size_t)row * KD))[t] = v;
        float a[4] = {v.x, v.y, v.z, v.w};
        __nv_bfloat16 h[4], m[4], l[4];
        #pragma unroll
        for (int k = 0; k < 4; k++) {
            h[k] = __float2bfloat16_rn(a[k]);
            float r1 = a[k] - __bfloat162float(h[k]);
            m[k] = __float2bfloat16_rn(r1);
            l[k] = __float2bfloat16_rn(r1 - __bfloat162float(m[k]));
        }
        size_t off = (size_t)row * KD + t * 4;
        *(uint2*)(e_hi + off)  = *(uint2*)h;
        *(uint2*)(e_mid + off) = *(uint2*)m;
        *(uint2*)(e_lo + off)  = *(uint2*)l;
    } else if (blk < 1280) {
        // --- W_in transpose + split3: (E,L)->(L,E), 32x32 tiles ---
        __shared__ float tbuf[32][33];
        int bi2 = blk - 1024;           // 0..255 = 16x16 tiles
        int bl = (bi2 & 15) * 32, be = (bi2 >> 4) * 32;
        int tx = tid & 31, ty = tid >> 5;   // 32 x 8
        #pragma unroll
        for (int i = 0; i < 32; i += 8)
            tbuf[ty + i][tx] = W_in[(size_t)(be + ty + i) * KD + bl + tx];
        __syncthreads();
        #pragma unroll
        for (int i = 0; i < 32; i += 8) {
            float a = tbuf[tx][ty + i];
            size_t o = (size_t)(bl + ty + i) * KD + be + tx;
            __nv_bfloat16 h = __float2bfloat16_rn(a);
            float r1 = a - __bfloat162float(h);
            __nv_bfloat16 m = __float2bfloat16_rn(r1);
            __nv_bfloat16 l = __float2bfloat16_rn(r1 - __bfloat162float(m));
            wt_hi[o] = h; wt_mid[o] = m; wt_lo[o] = l;
        }
    } else if (blk < 1536) {
        // --- cvec: c[n] = (emb_n / ||emb_n||) . b_in, warp per row ---
        // recompute norm locally from emb (no dependence on section A output)
        int warp = tid >> 5, lane = tid & 31;
        int n = (blk - 1280) * 8 + warp;
        const float* er = emb + (size_t)n * KD;
        float ss = 0.f, dp = 0.f;
        for (int i = lane; i < KD; i += 32) {
            float e = er[i];
            ss += e * e;
            dp += e * b_in[i];
        }
        #pragma unroll
        for (int o = 16; o > 0; o >>= 1) {
            ss += __shfl_down_sync(0xffffffffu, ss, o);
            dp += __shfl_down_sync(0xffffffffu, dp, o);
        }
        if (lane == 0) cvec[n] = dp / fmaxf(sqrtf(ss), 1e-12f);
    } else if (blk < 1792) {
        // --- W_out 2-way split (65536 float4, one per thread) ---
        int i = (blk - 1536) * 256 + tid;
        float4 v = ((const float4*)W_out)[i];
        __nv_bfloat16 h[4], l[4];
        float a[4] = {v.x, v.y, v.z, v.w};
        #pragma unroll
        for (int k = 0; k < 4; k++) {
            h[k] = __float2bfloat16_rn(a[k]);
            l[k] = __float2bfloat16_rn(a[k] - __bfloat162float(h[k]));
        }
        ((uint2*)wout_hi)[i] = *(uint2*)h;
        ((uint2*)wout_lo)[i] = *(uint2*)l;
    } else if (blk < 1920) {
        // --- zero rowmax / ccnt ---
        int i = (blk - 1792) * 256 + tid;
        rowmax[i] = 0u; ccnt[i] = 0;
    } else {
        // --- z -> bf16: grid-stride over 4M float4 ---
        const int NB = 3200 - 1920;
        for (int i = (blk - 1920) * 256 + tid; i < M_ROWS * KD / 4; i += NB * 256) {
            float4 v = ((const float4*)z)[i];
            __nv_bfloat16 h[4] = {__float2bfloat16_rn(v.x), __float2bfloat16_rn(v.y),
                                  __float2bfloat16_rn(v.z), __float2bfloat16_rn(v.w)};
            ((uint2*)z_bf)[i] = *(uint2*)h;
        }
    }
}

__global__ void tobf16_kernel(const float* __restrict__ src,
                              __nv_bfloat16* __restrict__ dst, int n4) {
    for (int i = blockIdx.x * 256 + threadIdx.x; i < n4; i += gridDim.x * 256) {
        float4 v = ((const float4*)src)[i];
        __nv_bfloat16 h[4] = {__float2bfloat16_rn(v.x), __float2bfloat16_rn(v.y),
                              __float2bfloat16_rn(v.z), __float2bfloat16_rn(v.w)};
        ((uint2*)dst)[i] = *(uint2*)h;
    }
}

// ---------------- smem tile: 128 rows x 32 bf16, XOR swizzle ---------------
__device__ __forceinline__ void load_tile_ca(const __nv_bfloat16* __restrict__ src,
                                             int rowBase, int kc, uint32_t dstBase, int tid) {
    #pragma unroll
    for (int u = 0; u < 2; u++) {
        int e = tid + u * 256;
        int r = e >> 2, c = e & 3;
        const __nv_bfloat16* g = src + (size_t)(rowBase + r) * KD + kc + c * 8;
        CP_ASYNC16(dstBase + r * 64 + ((c ^ ((r >> 1) & 3)) * 16), g);
    }
}

__device__ __forceinline__ void mma_pair(uint32_t stA, uint32_t stB,
                                         int lane, int warp_m, int warp_n, int ks,
                                         float acc[4][4][4]) {
    uint32_t a[4][4], b[4][2];
    #pragma unroll
    for (int mi = 0; mi < 4; mi++) {
        int row = warp_m * 64 + mi * 16 + (lane & 15);
        int ch  = ks * 2 + (lane >> 4);
        ldmx4(a[mi], stA + row * 64 + ((ch ^ ((row >> 1) & 3)) * 16));
    }
    #pragma unroll
    for (int p = 0; p < 2; p++) {
        int g = lane >> 3;
        int row = warp_n * 32 + p * 16 + ((g & 2) << 2) + (lane & 7);
        int ch  = ks * 2 + (g & 1);
        uint32_t r[4];
        ldmx4(r, stB + row * 64 + ((ch ^ ((row >> 1) & 3)) * 16));
        b[2*p][0] = r[0]; b[2*p][1] = r[1];
        b[2*p+1][0] = r[2]; b[2*p+1][1] = r[3];
    }
    #pragma unroll
    for (int mi = 0; mi < 4; mi++)
        #pragma unroll
        for (int ni = 0; ni < 4; ni++)
            mma_bf16(acc[mi][ni], a[mi], b[ni]);
}

// ---------------- general GEMM (128x128 tile, 2-stage) ---------------------
template<int TERMS, bool BIAS>
__global__ void __launch_bounds__(256) vq_gemm_kernel(
        const __nv_bfloat16* __restrict__ A0, const __nv_bfloat16* __restrict__ A1,
        const __nv_bfloat16* __restrict__ A2,
        const __nv_bfloat16* __restrict__ B0, const __nv_bfloat16* __restrict__ B1,
        const __nv_bfloat16* __restrict__ B2,
        const float* __restrict__ bias, float* __restrict__ C, int Ncols) {
    extern __shared__ char smem[];
    const int NL    = (TERMS == 6) ? 3 : (TERMS == 3) ? 2 : 1;
    const int STAGE = NL * 2 * 8192;
    uint32_t sb = smem_u32(smem);
    int tid = threadIdx.x, lane = tid & 31, wid = tid >> 5;
    int warp_m = wid & 1, warp_n = wid >> 1;
    int rowBase = blockIdx.y * 128;
    int colBase = blockIdx.x * 128;

    const __nv_bfloat16* As[3] = {A0, A1, A2};
    const __nv_bfloat16* Bs[3] = {B0, B1, B2};

    float acc[4][4][4];
    #pragma unroll
    for (int mi = 0; mi < 4; mi++)
        #pragma unroll
        for (int ni = 0; ni < 4; ni++)
            #pragma unroll
            for (int q = 0; q < 4; q++) acc[mi][ni][q] = 0.0f;

    #pragma unroll
    for (int l = 0; l < NL; l++) {
        load_tile_ca(As[l], rowBase, 0, sb + (2*l)   * 8192, tid);
        load_tile_ca(Bs[l], colBase, 0, sb + (2*l+1) * 8192, tid);
    }
    CP_COMMIT();

    const int KT = KD / 32;
    for (int kt = 0; kt < KT; kt++) {
        int s = kt & 1;
        if (kt + 1 < KT) {
            uint32_t st = sb + (s ^ 1) * STAGE;
            int kc = (kt + 1) * 32;
            #pragma unroll
            for (int l = 0; l < NL; l++) {
                load_tile_ca(As[l], rowBase, kc, st + (2*l)   * 8192, tid);
                load_tile_ca(Bs[l], colBase, kc, st + (2*l+1) * 8192, tid);
            }
            CP_COMMIT();
            CP_WAIT(1);
        } else {
            CP_WAIT(0);
        }
        __syncthreads();

        uint32_t st = sb + s * STAGE;
        uint32_t tA[3], tB[3];
        #pragma unroll
        for (int l = 0; l < NL; l++) { tA[l] = st + (2*l)*8192; tB[l] = st + (2*l+1)*8192; }

        #pragma unroll
        for (int ks = 0; ks < 2; ks++) {
            mma_pair(tA[0], tB[0], lane, warp_m, warp_n, ks, acc);
            if (TERMS >= 3) {
                mma_pair(tA[0], tB[NL-1], lane, warp_m, warp_n, ks, acc);
                mma_pair(tA[NL-1], tB[0], lane, warp_m, warp_n, ks, acc);
            }
            if (TERMS == 6) {
                mma_pair(tA[0], tB[1], lane, warp_m, warp_n, ks, acc);
                mma_pair(tA[1], tB[0], lane, warp_m, warp_n, ks, acc);
                mma_pair(tA[1], tB[1], lane, warp_m, warp_n, ks, acc);
            }
        }
        __syncthreads();
    }

    #pragma unroll
    for (int mi = 0; mi < 4; mi++) {
        int r0 = rowBase + warp_m * 64 + mi * 16 + (lane >> 2);
        #pragma unroll
        for (int ni = 0; ni < 4; ni++) {
            int col = colBase + warp_n * 32 + ni * 8 + (lane & 3) * 2;
            float b0 = BIAS ? bias[col]     : 0.0f;
            float b1 = BIAS ? bias[col + 1] : 0.0f;
            float2 v0 = {acc[mi][ni][0] + b0, acc[mi][ni][1] + b1};
            float2 v1 = {acc[mi][ni][2] + b0, acc[mi][ni][3] + b1};
            *(float2*)(C + (size_t)r0 * Ncols + col)       = v0;
            *(float2*)(C + (size_t)(r0 + 8) * Ncols + col) = v1;
        }
    }
}

// ---------------- scores GEMM: PROVEN R12/R15 config (frozen) --------------
__global__ void __launch_bounds__(256) vq_score_kernel(
        const __nv_bfloat16* __restrict__ A, const __nv_bfloat16* __restrict__ B,
        const float* __restrict__ cvec, unsigned* __restrict__ rowMax,
        int* __restrict__ ccnt, int* __restrict__ cand) {
    extern __shared__ char smem[];
    const int STAGE = 16384;
    uint32_t sb = smem_u32(smem);
    int tid = threadIdx.x, lane = tid & 31, wid = tid >> 5;
    int warp_m = wid & 1, warp_n = wid >> 1;
    int rowBase = blockIdx.x * 128;
    int colBase = blockIdx.y * 128;

    float acc[4][4][4];
    #pragma unroll
    for (int mi = 0; mi < 4; mi++)
        #pragma unroll
        for (int ni = 0; ni < 4; ni++)
            #pragma unroll
            for (int q = 0; q < 4; q++) acc[mi][ni][q] = 0.0f;

    load_tile_ca(A, rowBase, 0, sb, tid);
    load_tile_ca(B, colBase, 0, sb + 8192, tid);
    CP_COMMIT();

    const int KT = KD / 32;
    for (int kt = 0; kt < KT; kt++) {
        int s = kt & 1;
        if (kt + 1 < KT) {
            uint32_t st = sb + (s ^ 1) * STAGE;
            load_tile_ca(A, rowBase, (kt + 1) * 32, st, tid);
            load_tile_ca(B, colBase, (kt + 1) * 32, st + 8192, tid);
            CP_COMMIT();
            CP_WAIT(1);
        } else {
            CP_WAIT(0);
        }
        __syncthreads();

        uint32_t stA = sb + s * STAGE;
        #pragma unroll
        for (int ks = 0; ks < 2; ks++)
            mma_pair(stA, stA + 8192, lane, warp_m, warp_n, ks, acc);
        __syncthreads();
    }

    // fused epilogue: bias + rowmax + candidate push
    #pragma unroll
    for (int ni = 0; ni < 4; ni++) {
        int col = colBase + warp_n * 32 + ni * 8 + (lane & 3) * 2;
        float b0 = cvec[col], b1 = cvec[col + 1];
        #pragma unroll
        for (int mi = 0; mi < 4; mi++) {
            acc[mi][ni][0] += b0; acc[mi][ni][1] += b1;
            acc[mi][ni][2] += b0; acc[mi][ni][3] += b1;
        }
    }
    unsigned* rmax = (unsigned*)smem;
    if (tid < 128) rmax[tid] = 0u;
    __syncthreads();
    #pragma unroll
    for (int mi = 0; mi < 4; mi++) {
        int rl = warp_m * 64 + mi * 16 + (lane >> 2);
        float m0 = -1e30f, m1 = -1e30f;
        #pragma unroll
        for (int ni = 0; ni < 4; ni++) {
            m0 = fmaxf(m0, fmaxf(acc[mi][ni][0], acc[mi][ni][1]));
            m1 = fmaxf(m1, fmaxf(acc[mi][ni][2], acc[mi][ni][3]));
        }
        atomicMax(&rmax[rl],     fenc(m0));
        atomicMax(&rmax[rl + 8], fenc(m1));
    }
    __syncthreads();
    if (tid < 128) {
        unsigned mine = rmax[tid];
        unsigned old = atomicMax(&rowMax[rowBase + tid], mine);
        rmax[tid] = (old > mine) ? old : mine;
    }
    __syncthreads();
    #pragma unroll
    for (int mi = 0; mi < 4; mi++) {
        int rl = warp_m * 64 + mi * 16 + (lane >> 2);
        int r0 = rowBase + rl, r1 = r0 + 8;
        float t0 = fdec(rmax[rl]) - MARGIN;
        float t1 = fdec(rmax[rl + 8]) - MARGIN;
        #pragma unroll
        for (int ni = 0; ni < 4; ni++) {
            int col = colBase + warp_n * 32 + ni * 8 + (lane & 3) * 2;
            if (acc[mi][ni][0] >= t0) { int q = atomicAdd(&ccnt[r0], 1); if (q < NSLOT) cand[r0*NSLOT+q] = col; }
            if (acc[mi][ni][1] >= t0) { int q = atomicAdd(&ccnt[r0], 1); if (q < NSLOT) cand[r0*NSLOT+q] = col+1; }
            if (acc[mi][ni][2] >= t1) { int q = atomicAdd(&ccnt[r1], 1); if (q < NSLOT) cand[r1*NSLOT+q] = col; }
            if (acc[mi][ni][3] >= t1) { int q = atomicAdd(&ccnt[r1], 1); if (q < NSLOT) cand[r1*NSLOT+q] = col+1; }
        }
    }
}

// ---------------- rerank + fused output gather ------------------------------
__global__ void __launch_bounds__(256) rerank_gather_kernel(
        const int* __restrict__ ccnt, const int* __restrict__ cand,
        const float* __restrict__ z, const float* __restrict__ G,
        const float* __restrict__ cvec, const float* __restrict__ table,
        float* __restrict__ out, float* __restrict__ outTail) {
    int warp = threadIdx.x >> 5, lane = threadIdx.x & 31;
    int row = blockIdx.x * 8 + warp;

    int nc = ccnt[row];
    int bi;
    if (nc == 1) {
        bi = cand[row * NSLOT];
    } else {
        float zreg[16];
        const float* zr = z + (size_t)row * KD;
        #pragma unroll
        for (int k = 0; k < 16; k++) zreg[k] = zr[lane + 32 * k];
        float best = -1e30f; bi = 0x7fffffff;
        if (nc <= NSLOT) {
            for (int c = 0; c < nc; c++) {
                int ci = cand[row * NSLOT + c];
                const float* g = G + (size_t)ci * KD;
                float d = 0.f;
                #pragma unroll
                for (int k = 0; k < 16; k++) d = fmaf(zreg[k], g[lane + 32 * k], d);
                #pragma unroll
                for (int o = 16; o > 0; o >>= 1) d += __shfl_xor_sync(0xffffffffu, d, o);
                d += cvec[ci];
                if (d > best || (d == best && ci < bi)) { best = d; bi = ci; }
            }
        } else {
            for (int ci = 0; ci < NC; ci++) {
                const float* g = G + (size_t)ci * KD;
                float d = 0.f;
                #pragma unroll
                for (int k = 0; k < 16; k++) d = fmaf(zreg[k], g[lane + 32 * k], d);
                #pragma unroll
                for (int o = 16; o > 0; o >>= 1) d += __shfl_xor_sync(0xffffffffu, d, o);
                d += cvec[ci];
                if (d > best) { best = d; bi = ci; }
            }
        }
    }

    const float4* src = (const float4*)(table + (size_t)bi * KD);
    float4* dst = (float4*)(out + (size_t)row * KD);
    #pragma unroll
    for (int j = 0; j < 4; j++) dst[lane + 32 * j] = src[lane + 32 * j];
    if (outTail && lane == 0) outTail[row] = (float)bi;
}

// ---------------------------------------------------------------------------
extern "C" void kernel_launch(void* const* d_in, const int* in_sizes, int n_in,
                              void* d_out, int out_size) {
    const float* z     = (const float*)d_in[0];
    const float* W_in  = (const float*)d_in[2];
    const float* b_in  = (const float*)d_in[3];
    const float* W_out = (const float*)d_in[4];
    const float* b_out = (const float*)d_in[5];
    const float* emb   = (const float*)d_in[6];
    float* out = (float*)d_out;

    __nv_bfloat16 *z_bf, *e_hi, *e_mid, *e_lo, *wt_hi, *wt_mid, *wt_lo;
    __nv_bfloat16 *wout_hi, *wout_lo, *G_bf;
    float *embn, *G, *cvec, *table;
    unsigned* rowmax;
    int *ccnt, *cand;
    cudaGetSymbolAddress((void**)&z_bf,   g_z_bf);
    cudaGetSymbolAddress((void**)&embn,   g_embn);
    cudaGetSymbolAddress((void**)&e_hi,   g_e_hi);
    cudaGetSymbolAddress((void**)&e_mid,  g_e_mid);
    cudaGetSymbolAddress((void**)&e_lo,   g_e_lo);
    cudaGetSymbolAddress((void**)&wt_hi,  g_wt_hi);
    cudaGetSymbolAddress((void**)&wt_mid, g_wt_mid);
    cudaGetSymbolAddress((void**)&wt_lo,  g_wt_lo);
    cudaGetSymbolAddress((void**)&wout_hi,g_wout_hi);
    cudaGetSymbolAddress((void**)&wout_lo,g_wout_lo);
    cudaGetSymbolAddress((void**)&G,      g_G);
    cudaGetSymbolAddress((void**)&G_bf,   g_G_bf);
    cudaGetSymbolAddress((void**)&cvec,   g_c);
    cudaGetSymbolAddress((void**)&table,  g_table);
    cudaGetSymbolAddress((void**)&rowmax, g_rowmax);
    cudaGetSymbolAddress((void**)&ccnt,   g_ccnt);
    cudaGetSymbolAddress((void**)&cand,   g_cand);

    const int SM_T6 = 2 * 6 * 8192;
    const int SM_T3 = 2 * 4 * 8192;
    const int SM_SC = 2 * 16384;
    cudaFuncSetAttribute(vq_gemm_kernel<6, false>, cudaFuncAttributeMaxDynamicSharedMemorySize, SM_T6);
    cudaFuncSetAttribute(vq_gemm_kernel<3, true >, cudaFuncAttributeMaxDynamicSharedMemorySize, SM_T3);
    cudaFuncSetAttribute(vq_score_kernel, cudaFuncAttributeMaxDynamicSharedMemorySize, SM_SC);

    // single fused prep launch (replaces 6 small kernels)
    prep_kernel<<<3200, 256>>>(z, emb, W_in, b_in, W_out,
                               embn, e_hi, e_mid, e_lo,
                               wt_hi, wt_mid, wt_lo, wout_hi, wout_lo,
                               cvec, rowmax, ccnt, z_bf);

    // G = embn @ W_in  (fp32-grade via 6-term)
    vq_gemm_kernel<6, false><<<dim3(4, 16), 256, SM_T6>>>(
        e_hi, e_mid, e_lo, wt_hi, wt_mid, wt_lo, nullptr, G, KD);
    tobf16_kernel<<<256, 256>>>(G, G_bf, NC * KD / 4);

    // code table T = embn @ W_out^T + b_out  (A split = (hi, mid))
    vq_gemm_kernel<3, true><<<dim3(4, 16), 256, SM_T3>>>(
        e_hi, e_mid, nullptr, wout_hi, wout_lo, nullptr, b_out, table, KD);

    // scores GEMM (frozen config) with fused rowmax + candidate push
    vq_score_kernel<<<dim3(256, 16), 256, SM_SC>>>(
        z_bf, G_bf, cvec, rowmax, ccnt, cand);

    // rerank (nc==1 fast path) + fused output gather + index tail
    float* outTail = (out_size >= M_ROWS * KD + M_ROWS) ? (out + (size_t)M_ROWS * KD) : nullptr;
    rerank_gather_kernel<<<M_ROWS / 8, 256>>>(
        ccnt, cand, z, G, cvec, table, out, outTail);
}